// round 8
// baseline (speedup 1.0000x reference)
#include <cuda_runtime.h>
#include <cuda_fp16.h>
#include <cstdint>
#include <math.h>

// DataTransformer via mma.sync, fp16 hi/lo 2-pass split (hh + lh):
//   out[r,e] = sum_t softmax_t(cos(x_r,p_t)) * (x_r . W_t[e,:] + b_t[e]) + x[r,e]
// x [65536,128] f32, W [8,128,128] (W[t][e][d]), b [8,128], p [8,128].
// CTA tile: 128 rows x 64 cols, 512 threads (16 warps, warp tile 16x32). 2 CTAs/SM.

#define D_DIM   128
#define T_DIM   8
#define MTILE   128
#define NTILE   64
#define THREADS 512
#define NROWS   65536

// fp16 scratch (static __device__ arrays: allowed scratch form)
__device__ __half g_xhi[NROWS * D_DIM];
__device__ __half g_xlo[NROWS * D_DIM];
__device__ __half g_whi[T_DIM * D_DIM * D_DIM];

// ---- smem layout (bytes). Tiles use 256 B rows + XOR-of-16B-chunk swizzle ----
#define OFF_XHI  0u         // 128x128 fp16 = 32768
#define OFF_XLO  32768u
#define OFF_W    65536u     // 2 buffers x (64x128 fp16 = 16384) = 32768
#define OFF_P    98304u     // 8*128 f32 = 4096
#define OFF_B    102400u    // 8*64 f32 (this CTA's N-half) = 2048
#define OFF_SIM  104448u    // 128*9*4 = 4608
#define OFF_PN2  109056u    // 8 f32
#define SMEM_TOTAL 109088

__device__ __forceinline__ uint32_t smem_u32(const void* p) {
    uint32_t a;
    asm("{ .reg .u64 t; cvta.to.shared.u64 t, %1; cvt.u32.u64 %0, t; }" : "=r"(a) : "l"(p));
    return a;
}

#define CP_ASYNC16(dst, src) \
    asm volatile("cp.async.cg.shared.global [%0], [%1], 16;" :: "r"(dst), "l"(src) : "memory")
#define CP_COMMIT() asm volatile("cp.async.commit_group;" ::: "memory")
#define CP_WAIT1()  asm volatile("cp.async.wait_group 1;" ::: "memory")
#define CP_WAIT0()  asm volatile("cp.async.wait_group 0;" ::: "memory")

#define LDM4(r0, r1, r2, r3, addr) \
    asm volatile("ldmatrix.sync.aligned.m8n8.x4.shared.b16 {%0,%1,%2,%3}, [%4];" \
        : "=r"(r0), "=r"(r1), "=r"(r2), "=r"(r3) : "r"(addr))

#define MMA16816(d, a0, a1, a2, a3, b0, b1) \
    asm volatile("mma.sync.aligned.m16n8k16.row.col.f32.f16.f16.f32 " \
        "{%0,%1,%2,%3}, {%4,%5,%6,%7}, {%8,%9}, {%0,%1,%2,%3};" \
        : "+f"((d)[0]), "+f"((d)[1]), "+f"((d)[2]), "+f"((d)[3]) \
        : "r"(a0), "r"(a1), "r"(a2), "r"(a3), "r"(b0), "r"(b1))

// swizzled byte offset of 16B chunk (r, c), c in [0,16), 256 B rows
__device__ __forceinline__ uint32_t swz(int r, int c) {
    return (uint32_t)(r * 256 + ((c ^ (r & 7)) << 4));
}

// ===================== Kernel 1: fp32 -> fp16 hi/lo preconvert =====================
__global__ void conv_kernel(const float* __restrict__ x, const float* __restrict__ W)
{
    const int W4 = T_DIM * D_DIM * D_DIM / 4;   // 32768 float4
    const int X4 = NROWS * D_DIM / 4;           // 2097152 float4
    for (int i = blockIdx.x * blockDim.x + threadIdx.x; i < W4 + X4;
         i += gridDim.x * blockDim.x) {
        bool isw = (i < W4);
        float4 v = isw ? reinterpret_cast<const float4*>(W)[i]
                       : reinterpret_cast<const float4*>(x)[i - W4];
        float vf[4] = {v.x, v.y, v.z, v.w};
        uint32_t hw[4], lw[4];
#pragma unroll
        for (int e = 0; e < 4; e++) {
            __half h = __float2half_rn(vf[e]);
            __half l = __float2half_rn(vf[e] - __half2float(h));
            hw[e] = (uint32_t)__half_as_ushort(h);
            lw[e] = (uint32_t)__half_as_ushort(l);
        }
        uint2 hv = make_uint2(hw[0] | (hw[1] << 16), hw[2] | (hw[3] << 16));
        if (isw) {
            reinterpret_cast<uint2*>(g_whi)[i] = hv;
        } else {
            uint2 lv = make_uint2(lw[0] | (lw[1] << 16), lw[2] | (lw[3] << 16));
            reinterpret_cast<uint2*>(g_xhi)[i - W4] = hv;
            reinterpret_cast<uint2*>(g_xlo)[i - W4] = lv;
        }
    }
}

// ===================== Kernel 2: GEMM + gating + fold =====================
__device__ __forceinline__ void issue_w_tile(uint32_t sb, uint32_t wbuf, int t, int nbase, int tid)
{
    const size_t wb = (size_t)t * (D_DIM * D_DIM) + (size_t)nbase * D_DIM;
#pragma unroll
    for (int k = 0; k < 2; k++) {
        int ci = tid + k * THREADS;          // 16B chunk index, 1024 per tile (64 rows x 16)
        int r = ci >> 4, c = ci & 15;
        CP_ASYNC16(sb + wbuf + swz(r, c), g_whi + wb + r * D_DIM + c * 8);
    }
}

__global__ void __launch_bounds__(THREADS, 2)
dt_mma_kernel(const float* __restrict__ x,
              const float* __restrict__ b,
              const float* __restrict__ p,
              float* __restrict__ out)
{
    extern __shared__ char smem[];
    const uint32_t sb = smem_u32(smem);
    const int tid  = threadIdx.x;
    const int wid  = tid >> 5;
    const int lane = tid & 31;
    const int mblk = blockIdx.x >> 1;
    const int nblk = blockIdx.x & 1;
    const int row0 = mblk * MTILE;
    const int nbase = nblk * NTILE;

    float* s_p   = reinterpret_cast<float*>(smem + OFF_P);
    float* s_b   = reinterpret_cast<float*>(smem + OFF_B);
    float* s_sim = reinterpret_cast<float*>(smem + OFF_SIM);
    float* s_pn2 = reinterpret_cast<float*>(smem + OFF_PN2);

    // p (full) and b (this CTA's 64-col slice) to smem
#pragma unroll
    for (int i = tid; i < T_DIM * D_DIM; i += THREADS) s_p[i] = p[i];
    if (tid < T_DIM * NTILE)
        s_b[tid] = b[(tid >> 6) * D_DIM + nbase + (tid & 63)];

    // Group 0: x hi/lo tiles + W(0); Group 1: W(1)
#pragma unroll
    for (int k = 0; k < 4; k++) {
        int ci = tid + k * THREADS;          // 2048 chunks per x tile (128 rows x 16)
        int r = ci >> 4, c = ci & 15;
        const size_t gx = (size_t)(row0 + r) * D_DIM + c * 8;
        CP_ASYNC16(sb + OFF_XHI + swz(r, c), g_xhi + gx);
        CP_ASYNC16(sb + OFF_XLO + swz(r, c), g_xlo + gx);
    }
    issue_w_tile(sb, OFF_W, 0, nbase, tid);
    CP_COMMIT();
    issue_w_tile(sb, OFF_W + 16384u, 1, nbase, tid);
    CP_COMMIT();

    __syncthreads();   // s_p visible for gating

    // ---- Gating (exact fp32, overlapped with cp.async) ----
    if (tid < T_DIM) {
        float pn2 = 0.f;
#pragma unroll 16
        for (int d = 0; d < D_DIM; d++) {
            float pv = s_p[tid * D_DIM + d];
            pn2 = fmaf(pv, pv, pn2);
        }
        s_pn2[tid] = pn2;
    }
    float dots[T_DIM], xn2 = 0.f;
    if (tid < MTILE) {
#pragma unroll
        for (int t = 0; t < T_DIM; t++) dots[t] = 0.f;
        const float4* xr = reinterpret_cast<const float4*>(x + (size_t)(row0 + tid) * D_DIM);
#pragma unroll 4
        for (int i = 0; i < 32; i++) {
            float4 v = xr[i];
            float vf[4] = {v.x, v.y, v.z, v.w};
#pragma unroll
            for (int e = 0; e < 4; e++) {
                float xv = vf[e];
                xn2 = fmaf(xv, xv, xn2);
                int d = i * 4 + e;
#pragma unroll
                for (int t = 0; t < T_DIM; t++)
                    dots[t] = fmaf(xv, s_p[t * D_DIM + d], dots[t]);
            }
        }
    }
    __syncthreads();   // s_pn2 ready
    if (tid < MTILE) {
        float xn = sqrtf(xn2);
        float cosv[T_DIM], m = -1e30f;
#pragma unroll
        for (int t = 0; t < T_DIM; t++) {
            cosv[t] = dots[t] / (xn * sqrtf(s_pn2[t]));
            m = fmaxf(m, cosv[t]);
        }
        float ev[T_DIM], sum = 0.f;
#pragma unroll
        for (int t = 0; t < T_DIM; t++) { ev[t] = expf(cosv[t] - m); sum += ev[t]; }
        float inv = 1.f / sum;
#pragma unroll
        for (int t = 0; t < T_DIM; t++) s_sim[tid * 9 + t] = ev[t] * inv;
    }

    CP_WAIT1();        // group 0 (x + W0) complete
    __syncthreads();   // tiles + sim visible

    // ---- Warp tiling: 8(M) x 2(N) grid, warp tile 16x32 ----
    const int wm = wid & 7, wn = wid >> 3;
    const int mbw = wm * 16, nbw = wn * 32;

    // ldmatrix per-lane address parts (swizzled)
    const uint32_t arowb = (uint32_t)((mbw + (lane & 15)) * 256);
    const int     achnk  = lane >> 4;            // 0/1
    const uint32_t browb = (uint32_t)((nbw + (lane & 7) + ((lane >> 4) << 3)) * 256);
    const int     bchnk  = (lane >> 3) & 1;
    const int     bank   = lane & 7;             // == row&7 for both A and B lane->row maps
    const int rql = lane >> 2;
    const int cpl = (lane & 3) * 2;

    float acc[4][4];
#pragma unroll
    for (int j = 0; j < 4; j++)
#pragma unroll
        for (int e = 0; e < 4; e++) acc[j][e] = 0.f;

    for (int t = 0; t < T_DIM; t++) {
        const uint32_t wb = OFF_W + (uint32_t)(t & 1) * 16384u;

        float y[4][4];
#pragma unroll
        for (int j = 0; j < 4; j++)
#pragma unroll
            for (int e = 0; e < 4; e++) y[j][e] = 0.f;

#pragma unroll
        for (int k = 0; k < 8; k++) {
            const uint32_t aoff = arowb + (uint32_t)((((2 * k + achnk) ^ bank)) << 4);
            const uint32_t boff = browb + (uint32_t)((((2 * k + bchnk) ^ bank)) << 4);

            uint32_t ah0, ah1, ah2, ah3;
            LDM4(ah0, ah1, ah2, ah3, sb + OFF_XHI + aoff);
            uint32_t bh0, bh1, bh2, bh3, bh4, bh5, bh6, bh7;
            LDM4(bh0, bh1, bh2, bh3, sb + wb + boff);
            LDM4(bh4, bh5, bh6, bh7, sb + wb + boff + 16u * 256u);

            // pass hh
            MMA16816(y[0], ah0, ah1, ah2, ah3, bh0, bh1);
            MMA16816(y[1], ah0, ah1, ah2, ah3, bh2, bh3);
            MMA16816(y[2], ah0, ah1, ah2, ah3, bh4, bh5);
            MMA16816(y[3], ah0, ah1, ah2, ah3, bh6, bh7);

            // pass lh
            uint32_t al0, al1, al2, al3;
            LDM4(al0, al1, al2, al3, sb + OFF_XLO + aoff);
            MMA16816(y[0], al0, al1, al2, al3, bh0, bh1);
            MMA16816(y[1], al0, al1, al2, al3, bh2, bh3);
            MMA16816(y[2], al0, al1, al2, al3, bh4, bh5);
            MMA16816(y[3], al0, al1, al2, al3, bh6, bh7);
        }

        // fold: acc += sim_row * (y + bias_col)
        {
            const int rloc = mbw + rql;
            const float s0 = s_sim[rloc * 9 + t];
            const float s1 = s_sim[(rloc + 8) * 9 + t];
#pragma unroll
            for (int nt = 0; nt < 4; nt++) {
                const int c = nbw + nt * 8 + cpl;          // local col 0..63
                const float bb0 = s_b[t * NTILE + c];
                const float bb1 = s_b[t * NTILE + c + 1];
                acc[nt][0] = fmaf(s0, y[nt][0] + bb0, acc[nt][0]);
                acc[nt][1] = fmaf(s0, y[nt][1] + bb1, acc[nt][1]);
                acc[nt][2] = fmaf(s1, y[nt][2] + bb0, acc[nt][2]);
                acc[nt][3] = fmaf(s1, y[nt][3] + bb1, acc[nt][3]);
            }
        }

        // pipeline: refill the buffer we just finished with W(t+2)
        if (t < T_DIM - 2) {
            __syncthreads();
            issue_w_tile(sb, OFF_W + (uint32_t)(t & 1) * 16384u, t + 2, nbase, tid);
            CP_COMMIT();
        }
        if (t < T_DIM - 1) {
            if (t < T_DIM - 2) { CP_WAIT1(); } else { CP_WAIT0(); }
            __syncthreads();
        }
    }

    // ---- Epilogue: residual (exact fp32 x from gmem) + store ----
    {
        const int rg0 = row0 + mbw + rql;
        const int rg1 = rg0 + 8;
#pragma unroll
        for (int nt = 0; nt < 4; nt++) {
            const int c = nbase + nbw + nt * 8 + cpl;       // global col
            float2 xv0 = *reinterpret_cast<const float2*>(x + (size_t)rg0 * D_DIM + c);
            float2 o0  = make_float2(acc[nt][0] + xv0.x, acc[nt][1] + xv0.y);
            *reinterpret_cast<float2*>(out + (size_t)rg0 * D_DIM + c) = o0;
            float2 xv1 = *reinterpret_cast<const float2*>(x + (size_t)rg1 * D_DIM + c);
            float2 o1  = make_float2(acc[nt][2] + xv1.x, acc[nt][3] + xv1.y);
            *reinterpret_cast<float2*>(out + (size_t)rg1 * D_DIM + c) = o1;
        }
    }
}

extern "C" void kernel_launch(void* const* d_in, const int* in_sizes, int n_in,
                              void* d_out, int out_size)
{
    (void)n_in; (void)out_size;
    const float* x = (const float*)d_in[0];   // [B,S,D]
    const float* W = (const float*)d_in[1];   // [T,D,D]
    const float* b = (const float*)d_in[2];   // [T,D]
    const float* p = (const float*)d_in[3];   // [T,1,D]
    float* out = (float*)d_out;

    const int nrows = in_sizes[0] / D_DIM;    // 65536
    const int grid  = (nrows / MTILE) * 2;    // 1024 (M-blocks x 2 N-halves)

    conv_kernel<<<2048, 256>>>(x, W);

    cudaFuncSetAttribute(dt_mma_kernel,
                         cudaFuncAttributeMaxDynamicSharedMemorySize, SMEM_TOTAL);
    dt_mma_kernel<<<grid, THREADS, SMEM_TOTAL>>>(x, b, p, out);
}

// round 9
// speedup vs baseline: 1.5052x; 1.5052x over previous
#include <cuda_runtime.h>
#include <cuda_fp16.h>
#include <cstdint>
#include <math.h>

// DataTransformer via mma.sync, pure fp16 single-pass GEMM (fp32 accumulate):
//   out[r,e] = sum_t softmax_t(cos(x_r,p_t)) * (x_r . W_t[e,:] + b_t[e]) + x[r,e]
// x [65536,128] f32, W [8,128,128] (W[t][e][d]), b [8,128], p [8,128].
// Gating + bias + residual stay exact fp32. GEMM error ~1e-4 << 1e-3 threshold.
// CTA tile: 128 rows x 64 cols, 256 threads, warp grid 4x2 (tile 32x32). 2 CTAs/SM.

#define D_DIM   128
#define T_DIM   8
#define MTILE   128
#define NTILE   64
#define THREADS 256
#define NROWS   65536

// fp16 scratch (static __device__ arrays: allowed scratch form)
__device__ __half g_xhi[NROWS * D_DIM];
__device__ __half g_whi[T_DIM * D_DIM * D_DIM];

// ---- smem layout (bytes). Tiles use 256 B rows + XOR-of-16B-chunk swizzle ----
#define OFF_XHI  0u         // 128x128 fp16 = 32768
#define OFF_W    32768u     // 2 buffers x (64x128 fp16 = 16384) = 32768
#define OFF_P    65536u     // 8*128 f32 = 4096
#define OFF_B    69632u     // 8*64 f32 = 2048
#define OFF_SIM  71680u     // 128*9*4 = 4608
#define OFF_PN2  76288u     // 8 f32
#define SMEM_TOTAL 76320

__device__ __forceinline__ uint32_t smem_u32(const void* p) {
    uint32_t a;
    asm("{ .reg .u64 t; cvta.to.shared.u64 t, %1; cvt.u32.u64 %0, t; }" : "=r"(a) : "l"(p));
    return a;
}

#define CP_ASYNC16(dst, src) \
    asm volatile("cp.async.cg.shared.global [%0], [%1], 16;" :: "r"(dst), "l"(src) : "memory")
#define CP_COMMIT() asm volatile("cp.async.commit_group;" ::: "memory")
#define CP_WAIT1()  asm volatile("cp.async.wait_group 1;" ::: "memory")
#define CP_WAIT0()  asm volatile("cp.async.wait_group 0;" ::: "memory")

#define LDM4(r0, r1, r2, r3, addr) \
    asm volatile("ldmatrix.sync.aligned.m8n8.x4.shared.b16 {%0,%1,%2,%3}, [%4];" \
        : "=r"(r0), "=r"(r1), "=r"(r2), "=r"(r3) : "r"(addr))

#define MMA16816(d, a0, a1, a2, a3, b0, b1) \
    asm volatile("mma.sync.aligned.m16n8k16.row.col.f32.f16.f16.f32 " \
        "{%0,%1,%2,%3}, {%4,%5,%6,%7}, {%8,%9}, {%0,%1,%2,%3};" \
        : "+f"((d)[0]), "+f"((d)[1]), "+f"((d)[2]), "+f"((d)[3]) \
        : "r"(a0), "r"(a1), "r"(a2), "r"(a3), "r"(b0), "r"(b1))

// swizzled byte offset of 16B chunk (r, c), c in [0,16), 256 B rows
__device__ __forceinline__ uint32_t swz(int r, int c) {
    return (uint32_t)(r * 256 + ((c ^ (r & 7)) << 4));
}

// ===================== Kernel 1: fp32 -> fp16 preconvert =====================
__global__ void conv_kernel(const float* __restrict__ x, const float* __restrict__ W)
{
    const int W4 = T_DIM * D_DIM * D_DIM / 4;   // 32768 float4
    const int X4 = NROWS * D_DIM / 4;           // 2097152 float4
    for (int i = blockIdx.x * blockDim.x + threadIdx.x; i < W4 + X4;
         i += gridDim.x * blockDim.x) {
        bool isw = (i < W4);
        float4 v = isw ? reinterpret_cast<const float4*>(W)[i]
                       : reinterpret_cast<const float4*>(x)[i - W4];
        float vf[4] = {v.x, v.y, v.z, v.w};
        uint32_t hw[4];
#pragma unroll
        for (int e = 0; e < 4; e++)
            hw[e] = (uint32_t)__half_as_ushort(__float2half_rn(vf[e]));
        uint2 hv = make_uint2(hw[0] | (hw[1] << 16), hw[2] | (hw[3] << 16));
        if (isw) reinterpret_cast<uint2*>(g_whi)[i] = hv;
        else     reinterpret_cast<uint2*>(g_xhi)[i - W4] = hv;
    }
}

// ===================== Kernel 2: GEMM + gating + fold =====================
__device__ __forceinline__ void issue_w_tile(uint32_t sb, uint32_t wbuf, int t, int nbase, int tid)
{
    const size_t wb = (size_t)t * (D_DIM * D_DIM) + (size_t)nbase * D_DIM;
#pragma unroll
    for (int k = 0; k < 4; k++) {
        int ci = tid + k * THREADS;          // 16B chunk index, 1024 per tile (64 rows x 16)
        int r = ci >> 4, c = ci & 15;
        CP_ASYNC16(sb + wbuf + swz(r, c), g_whi + wb + r * D_DIM + c * 8);
    }
}

__global__ void __launch_bounds__(THREADS, 2)
dt_mma_kernel(const float* __restrict__ x,
              const float* __restrict__ b,
              const float* __restrict__ p,
              float* __restrict__ out)
{
    extern __shared__ char smem[];
    const uint32_t sb = smem_u32(smem);
    const int tid  = threadIdx.x;
    const int wid  = tid >> 5;
    const int lane = tid & 31;
    const int mblk = blockIdx.x >> 1;
    const int nblk = blockIdx.x & 1;
    const int row0 = mblk * MTILE;
    const int nbase = nblk * NTILE;

    float* s_p   = reinterpret_cast<float*>(smem + OFF_P);
    float* s_b   = reinterpret_cast<float*>(smem + OFF_B);
    float* s_sim = reinterpret_cast<float*>(smem + OFF_SIM);
    float* s_pn2 = reinterpret_cast<float*>(smem + OFF_PN2);

    // p (full) and b (this CTA's 64-col slice) to smem
#pragma unroll
    for (int i = tid; i < T_DIM * D_DIM; i += THREADS) s_p[i] = p[i];
#pragma unroll
    for (int i = tid; i < T_DIM * NTILE; i += THREADS)
        s_b[i] = b[(i >> 6) * D_DIM + nbase + (i & 63)];

    // Group 0: x tile + W(0); Group 1: W(1)
#pragma unroll
    for (int k = 0; k < 8; k++) {
        int ci = tid + k * THREADS;          // 2048 chunks per x tile (128 rows x 16)
        int r = ci >> 4, c = ci & 15;
        CP_ASYNC16(sb + OFF_XHI + swz(r, c), g_xhi + (size_t)(row0 + r) * D_DIM + c * 8);
    }
    issue_w_tile(sb, OFF_W, 0, nbase, tid);
    CP_COMMIT();
    issue_w_tile(sb, OFF_W + 16384u, 1, nbase, tid);
    CP_COMMIT();

    __syncthreads();   // s_p visible for gating

    // ---- Gating (exact fp32, overlapped with cp.async) ----
    if (tid < T_DIM) {
        float pn2 = 0.f;
#pragma unroll 16
        for (int d = 0; d < D_DIM; d++) {
            float pv = s_p[tid * D_DIM + d];
            pn2 = fmaf(pv, pv, pn2);
        }
        s_pn2[tid] = pn2;
    }
    float dots[T_DIM], xn2 = 0.f;
    if (tid < MTILE) {
#pragma unroll
        for (int t = 0; t < T_DIM; t++) dots[t] = 0.f;
        const float4* xr = reinterpret_cast<const float4*>(x + (size_t)(row0 + tid) * D_DIM);
#pragma unroll 4
        for (int i = 0; i < 32; i++) {
            float4 v = xr[i];
            float vf[4] = {v.x, v.y, v.z, v.w};
#pragma unroll
            for (int e = 0; e < 4; e++) {
                float xv = vf[e];
                xn2 = fmaf(xv, xv, xn2);
                int d = i * 4 + e;
#pragma unroll
                for (int t = 0; t < T_DIM; t++)
                    dots[t] = fmaf(xv, s_p[t * D_DIM + d], dots[t]);
            }
        }
    }
    __syncthreads();   // s_pn2 ready
    if (tid < MTILE) {
        float xn = sqrtf(xn2);
        float cosv[T_DIM], m = -1e30f;
#pragma unroll
        for (int t = 0; t < T_DIM; t++) {
            cosv[t] = dots[t] / (xn * sqrtf(s_pn2[t]));
            m = fmaxf(m, cosv[t]);
        }
        float ev[T_DIM], sum = 0.f;
#pragma unroll
        for (int t = 0; t < T_DIM; t++) { ev[t] = expf(cosv[t] - m); sum += ev[t]; }
        float inv = 1.f / sum;
#pragma unroll
        for (int t = 0; t < T_DIM; t++) s_sim[tid * 9 + t] = ev[t] * inv;
    }

    CP_WAIT1();        // group 0 (x + W0) complete
    __syncthreads();   // tiles + sim visible

    // ---- Warp tiling: 4(M) x 2(N) grid, warp tile 32x32 ----
    const int wm = wid & 3, wn = wid >> 2;
    const int mbw = wm * 32, nbw = wn * 32;

    // ldmatrix per-lane address parts (swizzled)
    const uint32_t arowb = (uint32_t)((mbw + (lane & 15)) * 256);
    const int     achnk  = lane >> 4;            // 0/1
    const uint32_t browb = (uint32_t)((nbw + (lane & 7) + ((lane >> 4) << 3)) * 256);
    const int     bchnk  = (lane >> 3) & 1;
    const int     bank   = lane & 7;             // == row&7 for both A and B lane->row maps
    const int rql = lane >> 2;
    const int cpl = (lane & 3) * 2;

    float acc[2][4][4];
#pragma unroll
    for (int i = 0; i < 2; i++)
#pragma unroll
        for (int j = 0; j < 4; j++)
#pragma unroll
            for (int e = 0; e < 4; e++) acc[i][j][e] = 0.f;

    for (int t = 0; t < T_DIM; t++) {
        const uint32_t wb = OFF_W + (uint32_t)(t & 1) * 16384u;

        float y[2][4][4];
#pragma unroll
        for (int i = 0; i < 2; i++)
#pragma unroll
            for (int j = 0; j < 4; j++)
#pragma unroll
                for (int e = 0; e < 4; e++) y[i][j][e] = 0.f;

#pragma unroll
        for (int k = 0; k < 8; k++) {
            const uint32_t aoff = arowb + (uint32_t)((((2 * k + achnk) ^ bank)) << 4);
            const uint32_t boff = browb + (uint32_t)((((2 * k + bchnk) ^ bank)) << 4);

            uint32_t ah0, ah1, ah2, ah3, ah4, ah5, ah6, ah7;
            LDM4(ah0, ah1, ah2, ah3, sb + OFF_XHI + aoff);
            LDM4(ah4, ah5, ah6, ah7, sb + OFF_XHI + aoff + 16u * 256u);
            uint32_t bh0, bh1, bh2, bh3, bh4, bh5, bh6, bh7;
            LDM4(bh0, bh1, bh2, bh3, sb + wb + boff);
            LDM4(bh4, bh5, bh6, bh7, sb + wb + boff + 16u * 256u);

            MMA16816(y[0][0], ah0, ah1, ah2, ah3, bh0, bh1);
            MMA16816(y[0][1], ah0, ah1, ah2, ah3, bh2, bh3);
            MMA16816(y[0][2], ah0, ah1, ah2, ah3, bh4, bh5);
            MMA16816(y[0][3], ah0, ah1, ah2, ah3, bh6, bh7);
            MMA16816(y[1][0], ah4, ah5, ah6, ah7, bh0, bh1);
            MMA16816(y[1][1], ah4, ah5, ah6, ah7, bh2, bh3);
            MMA16816(y[1][2], ah4, ah5, ah6, ah7, bh4, bh5);
            MMA16816(y[1][3], ah4, ah5, ah6, ah7, bh6, bh7);
        }

        // fold: acc += sim_row * (y + bias_col)
#pragma unroll
        for (int mt = 0; mt < 2; mt++) {
            const int rloc = mbw + mt * 16 + rql;
            const float s0 = s_sim[rloc * 9 + t];
            const float s1 = s_sim[(rloc + 8) * 9 + t];
#pragma unroll
            for (int nt = 0; nt < 4; nt++) {
                const int c = nbw + nt * 8 + cpl;          // local col 0..63
                const float bb0 = s_b[t * NTILE + c];
                const float bb1 = s_b[t * NTILE + c + 1];
                acc[mt][nt][0] = fmaf(s0, y[mt][nt][0] + bb0, acc[mt][nt][0]);
                acc[mt][nt][1] = fmaf(s0, y[mt][nt][1] + bb1, acc[mt][nt][1]);
                acc[mt][nt][2] = fmaf(s1, y[mt][nt][2] + bb0, acc[mt][nt][2]);
                acc[mt][nt][3] = fmaf(s1, y[mt][nt][3] + bb1, acc[mt][nt][3]);
            }
        }

        // pipeline: refill the buffer we just finished with W(t+2)
        if (t < T_DIM - 2) {
            __syncthreads();
            issue_w_tile(sb, OFF_W + (uint32_t)(t & 1) * 16384u, t + 2, nbase, tid);
            CP_COMMIT();
        }
        if (t < T_DIM - 1) {
            if (t < T_DIM - 2) { CP_WAIT1(); } else { CP_WAIT0(); }
            __syncthreads();
        }
    }

    // ---- Epilogue: residual (exact fp32 x from gmem) + store ----
#pragma unroll
    for (int mt = 0; mt < 2; mt++) {
        const int rg0 = row0 + mbw + mt * 16 + rql;
        const int rg1 = rg0 + 8;
#pragma unroll
        for (int nt = 0; nt < 4; nt++) {
            const int c = nbase + nbw + nt * 8 + cpl;       // global col
            float2 xv0 = *reinterpret_cast<const float2*>(x + (size_t)rg0 * D_DIM + c);
            float2 o0  = make_float2(acc[mt][nt][0] + xv0.x, acc[mt][nt][1] + xv0.y);
            *reinterpret_cast<float2*>(out + (size_t)rg0 * D_DIM + c) = o0;
            float2 xv1 = *reinterpret_cast<const float2*>(x + (size_t)rg1 * D_DIM + c);
            float2 o1  = make_float2(acc[mt][nt][2] + xv1.x, acc[mt][nt][3] + xv1.y);
            *reinterpret_cast<float2*>(out + (size_t)rg1 * D_DIM + c) = o1;
        }
    }
}

extern "C" void kernel_launch(void* const* d_in, const int* in_sizes, int n_in,
                              void* d_out, int out_size)
{
    (void)n_in; (void)out_size;
    const float* x = (const float*)d_in[0];   // [B,S,D]
    const float* W = (const float*)d_in[1];   // [T,D,D]
    const float* b = (const float*)d_in[2];   // [T,D]
    const float* p = (const float*)d_in[3];   // [T,1,D]
    float* out = (float*)d_out;

    const int nrows = in_sizes[0] / D_DIM;    // 65536
    const int grid  = (nrows / MTILE) * 2;    // 1024 (M-blocks x 2 N-halves)

    conv_kernel<<<2048, 256>>>(x, W);

    cudaFuncSetAttribute(dt_mma_kernel,
                         cudaFuncAttributeMaxDynamicSharedMemorySize, SMEM_TOTAL);
    dt_mma_kernel<<<grid, THREADS, SMEM_TOTAL>>>(x, b, p, out);
}